// round 3
// baseline (speedup 1.0000x reference)
#include <cuda_runtime.h>
#include <cuda_bf16.h>
#include <cstdint>

#define N_NODES 100000
#define N_EDGES 1600000
#define N_GRAPHS 256
#define D 128
#define L 3
#define PROJ 128
#define NUM_CLASSES 10

// ---------------- device scratch ----------------
__device__ float g_h[N_NODES * D];
__device__ float g_agg[N_NODES * D];
__device__ int   g_counts[N_NODES];
__device__ int   g_offs[N_NODES];
__device__ int   g_cursor[N_NODES];
__device__ int   g_bsum[128];
__device__ int   g_eidx[N_EDGES];
__device__ int   g_cg[N_GRAPHS];
__device__ float g_pooled[L * N_GRAPHS * D];
__device__ __align__(16) __nv_bfloat16 g_w1hi[L * D * D];
__device__ __align__(16) __nv_bfloat16 g_w1lo[L * D * D];
__device__ __align__(16) __nv_bfloat16 g_w2hi[L * D * D];
__device__ __align__(16) __nv_bfloat16 g_w2lo[L * D * D];
__device__ float g_b1e[L * D];
__device__ int   g_is64;

// ---------------- dtype detection: int64 vs int32 indices ----------------
// For int64 data with values < 2^31, every odd 32-bit word is 0.
__global__ void detect_kernel(const int* __restrict__ ei_words) {
    int all0 = 1;
    for (int i = 1; i < 128; i += 2)
        if (ei_words[i] != 0) { all0 = 0; break; }
    g_is64 = all0;
}

__device__ __forceinline__ int idx_at(const void* p, long long i) {
    if (g_is64) return (int)__ldg(&((const long long*)p)[i]);
    return __ldg(&((const int*)p)[i]);
}

// ---------------- setup kernels ----------------
__global__ void zero_kernel() {
    int i = blockIdx.x * blockDim.x + threadIdx.x;
    if (i < N_NODES) g_counts[i] = 0;
    if (i < N_GRAPHS) g_cg[i] = 0;
    if (i < L * N_GRAPHS * D) g_pooled[i] = 0.f;
}

__global__ void hist_edges(const void* __restrict__ ei) {
    int e = blockIdx.x * blockDim.x + threadIdx.x;
    if (e < N_EDGES) {
        int d = idx_at(ei, (long long)N_EDGES + e);
        atomicAdd(&g_counts[d], 1);
    }
}

__global__ void hist_batch(const void* __restrict__ batch) {
    int i = blockIdx.x * blockDim.x + threadIdx.x;
    if (i < N_NODES) atomicAdd(&g_cg[idx_at(batch, i)], 1);
}

__global__ void scan1() {
    __shared__ int s[1024];
    int i = blockIdx.x * 1024 + threadIdx.x;
    int v = (i < N_NODES) ? g_counts[i] : 0;
    s[threadIdx.x] = v;
    __syncthreads();
    for (int d = 1; d < 1024; d <<= 1) {
        int t = 0;
        if ((int)threadIdx.x >= d) t = s[threadIdx.x - d];
        __syncthreads();
        s[threadIdx.x] += t;
        __syncthreads();
    }
    if (i < N_NODES) g_offs[i] = s[threadIdx.x] - v;  // exclusive
    if (threadIdx.x == 1023) g_bsum[blockIdx.x] = s[1023];
}

__global__ void scan2() {
    int acc = 0;
    for (int b = 0; b < 98; b++) { int v = g_bsum[b]; g_bsum[b] = acc; acc += v; }
}

__global__ void scan3() {
    int i = blockIdx.x * blockDim.x + threadIdx.x;
    if (i < N_NODES) {
        int off = g_offs[i] + g_bsum[i >> 10];
        g_offs[i] = off;
        g_cursor[i] = off;
    }
}

__global__ void scatter_edges(const void* __restrict__ ei) {
    int e = blockIdx.x * blockDim.x + threadIdx.x;
    if (e < N_EDGES) {
        int d = idx_at(ei, (long long)N_EDGES + e);
        int s = idx_at(ei, e);
        int p = atomicAdd(&g_cursor[d], 1);
        g_eidx[p] = s;
    }
}

// Fold BN into W1/b1, transpose to [l][n][k], split to bf16 hi/lo.
__global__ void convert_weights(const float* __restrict__ W1, const float* __restrict__ W2,
                                const float* __restrict__ b1,
                                const float* __restrict__ bng, const float* __restrict__ bnb,
                                const float* __restrict__ bnm, const float* __restrict__ bnv) {
    int i = blockIdx.x * blockDim.x + threadIdx.x;
    if (i >= L * D * D) return;
    int l = i / (D * D);
    int rem = i % (D * D);
    int k = rem / D;
    int n = rem % D;
    float scale = bng[l * D + n] * rsqrtf(bnv[l * D + n] + 1e-5f);
    int o = l * D * D + n * D + k;
    float w1 = W1[i] * scale;
    __nv_bfloat16 h = __float2bfloat16(w1);
    g_w1hi[o] = h;
    g_w1lo[o] = __float2bfloat16(w1 - __bfloat162float(h));
    float w2 = W2[i];
    h = __float2bfloat16(w2);
    g_w2hi[o] = h;
    g_w2lo[o] = __float2bfloat16(w2 - __bfloat162float(h));
    if (k == 0) {
        g_b1e[l * D + n] = (b1[l * D + n] - bnm[l * D + n]) * scale + bnb[l * D + n];
    }
}

// ---------------- aggregation: agg[i] = h[i] + sum_{j->i} h[j] ----------------
__global__ void aggregate_kernel(const float* __restrict__ x, int l) {
    int wid = threadIdx.x >> 5, lane = threadIdx.x & 31;
    int node = blockIdx.x * 8 + wid;
    if (node >= N_NODES) return;
    const float4* h4 = (const float4*)((l == 0) ? x : (const float*)g_h);
    float4 acc = h4[node * 32 + lane];
    int s = g_offs[node];
    int e = s + g_counts[node];
    for (int i = s; i < e; i++) {
        int src = g_eidx[i];
        float4 v = __ldg(&h4[src * 32 + lane]);
        acc.x += v.x; acc.y += v.y; acc.z += v.z; acc.w += v.w;
    }
    ((float4*)g_agg)[node * 32 + lane] = acc;
}

// ---------------- fused MLP (Linear+BN+ReLU+Linear+ReLU) via bf16 3-term mma ----------------
__device__ __forceinline__ void mma_bf16(float* c,
                                         uint32_t a0, uint32_t a1, uint32_t a2, uint32_t a3,
                                         uint32_t b0, uint32_t b1) {
    asm volatile(
        "mma.sync.aligned.m16n8k16.row.col.f32.bf16.bf16.f32 "
        "{%0,%1,%2,%3}, {%4,%5,%6,%7}, {%8,%9}, {%0,%1,%2,%3};"
        : "+f"(c[0]), "+f"(c[1]), "+f"(c[2]), "+f"(c[3])
        : "r"(a0), "r"(a1), "r"(a2), "r"(a3), "r"(b0), "r"(b1));
}

#define SM_PITCH 136

__device__ __forceinline__ void gemm_pass(const __nv_bfloat16* sA, const __nv_bfloat16* wmat,
                                          int r0, int g, int t4, float acc[16][4]) {
#pragma unroll
    for (int kk = 0; kk < 8; kk++) {
        int kb = kk * 16 + t4 * 2;
        uint32_t a0 = *(const uint32_t*)(sA + r0 * SM_PITCH + kb);
        uint32_t a1 = *(const uint32_t*)(sA + (r0 + 8) * SM_PITCH + kb);
        uint32_t a2 = *(const uint32_t*)(sA + r0 * SM_PITCH + kb + 8);
        uint32_t a3 = *(const uint32_t*)(sA + (r0 + 8) * SM_PITCH + kb + 8);
#pragma unroll
        for (int nb = 0; nb < 16; nb++) {
            const __nv_bfloat16* wp = wmat + (nb * 8 + g) * 128 + kb;
            uint32_t b0 = *(const uint32_t*)wp;
            uint32_t b1 = *(const uint32_t*)(wp + 8);
            mma_bf16(acc[nb], a0, a1, a2, a3, b0, b1);
        }
    }
}

__device__ __forceinline__ void store_split(__nv_bfloat16* sHi, __nv_bfloat16* sLo,
                                            int r, int c, float x, float y) {
    __nv_bfloat16 hx = __float2bfloat16(x), hy = __float2bfloat16(y);
    unsigned int uh = (unsigned)(*(unsigned short*)&hx) | ((unsigned)(*(unsigned short*)&hy) << 16);
    __nv_bfloat16 lx = __float2bfloat16(x - __bfloat162float(hx));
    __nv_bfloat16 ly = __float2bfloat16(y - __bfloat162float(hy));
    unsigned int ul = (unsigned)(*(unsigned short*)&lx) | ((unsigned)(*(unsigned short*)&ly) << 16);
    *(unsigned int*)(sHi + r * SM_PITCH + c) = uh;
    *(unsigned int*)(sLo + r * SM_PITCH + c) = ul;
}

#define SMEM_MLP (2 * 128 * SM_PITCH * 2)

__global__ void __launch_bounds__(256) mlp_kernel(int l, const float* __restrict__ b2all) {
    extern __shared__ __nv_bfloat16 sm[];
    __nv_bfloat16* sHi = sm;
    __nv_bfloat16* sLo = sm + 128 * SM_PITCH;
    const int tid = threadIdx.x;
    const int tile = blockIdx.x * 128;

    // load agg tile, split to hi/lo bf16
    for (int i = tid; i < 128 * 128; i += 256) {
        int r = i >> 7, c = i & 127;
        int row = tile + r;
        float v = (row < N_NODES) ? g_agg[row * 128 + c] : 0.f;
        __nv_bfloat16 h = __float2bfloat16(v);
        sHi[r * SM_PITCH + c] = h;
        sLo[r * SM_PITCH + c] = __float2bfloat16(v - __bfloat162float(h));
    }
    __syncthreads();

    const int wid = tid >> 5, lane = tid & 31;
    const int g = lane >> 2, t4 = lane & 3;
    const int r0 = wid * 16 + g;

    const __nv_bfloat16* w1hi = g_w1hi + l * D * D;
    const __nv_bfloat16* w1lo = g_w1lo + l * D * D;
    const __nv_bfloat16* w2hi = g_w2hi + l * D * D;
    const __nv_bfloat16* w2lo = g_w2lo + l * D * D;
    const float* b1e = g_b1e + l * D;
    const float* b2 = b2all + l * D;

    float acc[16][4];
#pragma unroll
    for (int nb = 0; nb < 16; nb++)
#pragma unroll
        for (int j = 0; j < 4; j++) acc[nb][j] = 0.f;

    // GEMM1: 3-term compensated bf16
    gemm_pass(sHi, w1hi, r0, g, t4, acc);
    gemm_pass(sHi, w1lo, r0, g, t4, acc);
    gemm_pass(sLo, w1hi, r0, g, t4, acc);
    __syncthreads();  // everyone done reading A

    // epilogue1: +b1_eff (BN folded), relu, resplit to smem
#pragma unroll
    for (int nb = 0; nb < 16; nb++) {
        int c0 = nb * 8 + t4 * 2;
        float bb0 = b1e[c0], bb1 = b1e[c0 + 1];
        float v00 = fmaxf(acc[nb][0] + bb0, 0.f);
        float v01 = fmaxf(acc[nb][1] + bb1, 0.f);
        float v10 = fmaxf(acc[nb][2] + bb0, 0.f);
        float v11 = fmaxf(acc[nb][3] + bb1, 0.f);
        store_split(sHi, sLo, r0, c0, v00, v01);
        store_split(sHi, sLo, r0 + 8, c0, v10, v11);
    }
    __syncthreads();

#pragma unroll
    for (int nb = 0; nb < 16; nb++)
#pragma unroll
        for (int j = 0; j < 4; j++) acc[nb][j] = 0.f;

    // GEMM2
    gemm_pass(sHi, w2hi, r0, g, t4, acc);
    gemm_pass(sHi, w2lo, r0, g, t4, acc);
    gemm_pass(sLo, w2hi, r0, g, t4, acc);

    // epilogue2: +b2, relu, store h
    int row0 = tile + r0;
    int row1 = tile + r0 + 8;
#pragma unroll
    for (int nb = 0; nb < 16; nb++) {
        int c0 = nb * 8 + t4 * 2;
        float bb0 = b2[c0], bb1 = b2[c0 + 1];
        float v00 = fmaxf(acc[nb][0] + bb0, 0.f);
        float v01 = fmaxf(acc[nb][1] + bb1, 0.f);
        float v10 = fmaxf(acc[nb][2] + bb0, 0.f);
        float v11 = fmaxf(acc[nb][3] + bb1, 0.f);
        if (row0 < N_NODES) *(float2*)&g_h[row0 * 128 + c0] = make_float2(v00, v01);
        if (row1 < N_NODES) *(float2*)&g_h[row1 * 128 + c0] = make_float2(v10, v11);
    }
}

// ---------------- pooling: segment-sum of h into pooled[l] ----------------
// 128 threads per block (one per feature), each block walks a 256-node segment.
#define POOL_NODES 256
__global__ void pool_kernel(const void* __restrict__ batch, int l) {
    int t = threadIdx.x;  // 0..127 feature index
    int start = blockIdx.x * POOL_NODES;
    if (start >= N_NODES) return;
    int end = min(start + POOL_NODES, N_NODES);
    int cur = idx_at(batch, start);
    float acc = 0.f;
    for (int n = start; n < end; n++) {
        int gid = idx_at(batch, n);
        if (gid != cur) {
            atomicAdd(&g_pooled[(l * N_GRAPHS + cur) * D + t], acc);
            acc = 0.f;
            cur = gid;
        }
        acc += g_h[n * D + t];
    }
    atomicAdd(&g_pooled[(l * N_GRAPHS + cur) * D + t], acc);
}

// ---------------- head: z = concat(pooled)/denom @ Wp + bp ; logits = z @ Wc + bc ----------------
__global__ void head_kernel(const float* __restrict__ Wp, const float* __restrict__ bp,
                            const float* __restrict__ Wc, const float* __restrict__ bc,
                            float* __restrict__ out) {
    __shared__ float zs[PROJ];
    int gph = blockIdx.x, t = threadIdx.x;
    float inv = 1.f / fmaxf((float)g_cg[gph], 1.f);
    float acc = bp[t];
#pragma unroll
    for (int l = 0; l < L; l++) {
        const float* pl = &g_pooled[(l * N_GRAPHS + gph) * D];
#pragma unroll 4
        for (int k = 0; k < D; k++) acc += pl[k] * inv * Wp[(l * D + k) * PROJ + t];
    }
    zs[t] = acc;
    out[gph * PROJ + t] = acc;
    __syncthreads();
    if (t < NUM_CLASSES) {
        float la = bc[t];
        for (int k = 0; k < PROJ; k++) la += zs[k] * Wc[k * NUM_CLASSES + t];
        out[N_GRAPHS * PROJ + gph * NUM_CLASSES + t] = la;
    }
}

// ---------------- launch ----------------
extern "C" void kernel_launch(void* const* d_in, const int* in_sizes, int n_in,
                              void* d_out, int out_size) {
    const float* x = (const float*)d_in[0];
    const void* ei = d_in[1];
    const void* batch = d_in[2];
    const float* W1 = (const float*)d_in[3];
    const float* b1 = (const float*)d_in[4];
    const float* bng = (const float*)d_in[5];
    const float* bnb = (const float*)d_in[6];
    const float* bnm = (const float*)d_in[7];
    const float* bnv = (const float*)d_in[8];
    const float* W2 = (const float*)d_in[9];
    const float* b2 = (const float*)d_in[10];
    const float* Wp = (const float*)d_in[11];
    const float* bp = (const float*)d_in[12];
    const float* Wc = (const float*)d_in[13];
    const float* bc = (const float*)d_in[14];
    float* out = (float*)d_out;

    cudaFuncSetAttribute(mlp_kernel, cudaFuncAttributeMaxDynamicSharedMemorySize, SMEM_MLP);

    detect_kernel<<<1, 1>>>((const int*)ei);
    zero_kernel<<<400, 256>>>();
    hist_edges<<<(N_EDGES + 255) / 256, 256>>>(ei);
    hist_batch<<<(N_NODES + 255) / 256, 256>>>(batch);
    scan1<<<98, 1024>>>();
    scan2<<<1, 1>>>();
    scan3<<<(N_NODES + 255) / 256, 256>>>();
    scatter_edges<<<(N_EDGES + 255) / 256, 256>>>(ei);
    convert_weights<<<(L * D * D + 255) / 256, 256>>>(W1, W2, b1, bng, bnb, bnm, bnv);

    for (int l = 0; l < L; l++) {
        aggregate_kernel<<<12500, 256>>>(x, l);
        mlp_kernel<<<(N_NODES + 127) / 128, 256, SMEM_MLP>>>(l, b2);
        pool_kernel<<<(N_NODES + POOL_NODES - 1) / POOL_NODES, 128>>>(batch, l);
    }
    head_kernel<<<N_GRAPHS, PROJ>>>(Wp, bp, Wc, bc, out);
}